// round 7
// baseline (speedup 1.0000x reference)
#include <cuda_runtime.h>

// Problem constants (fixed by setup_inputs)
#define BB  2
#define CC  32
#define TT  64
#define HH  64
#define WW  64
#define HWSZ 4096          // H*W
#define NN  512
#define CF  32
#define CHN 16
#define FT  400            // featT == orgt == 400
#define LL  (FT*NN)        // 204800
#define BL  (BB*LL)        // 409600
#define NBLK_S (BB*TT)     // 128 stat blocks
#define T_SCALE (63.0f/399.0f)
#define EPS 1e-5f

// Scratch (static device allocations; no cudaMalloc allowed)
__device__ float g_hx[BB*CHN*TT*NN];    // W1f@gather(x) at source T: [b][o][t][n]  4 MB
__device__ float g_r [BB*TT*HWSZ];      // Wr@x head: [b][t][hw]   2 MB
__device__ float g_W1f[CHN*CF];
__device__ float g_b1f[CHN];
__device__ float g_part[NBLK_S*32];     // per-block partials (16 sum + 16 sumsq)
__device__ float g_stats[32];
// interpolation weight tables per source interval s (bucket = i0(t))
__device__ float g_Sa[64], g_Sb[64];               // sum weights
__device__ float g_Qa[64], g_Qab[64], g_Qb[64];    // sumsq weights
__device__ int   g_tstart[65];                     // t-range per bucket

// ---------------------------------------------------------------------------
// K0: fuse W1@Wf -> W1f, W1@bf + b1 -> b1f; scan t to build weight tables.
__global__ void __launch_bounds__(512)
k_prep(const float* __restrict__ W1, const float* __restrict__ b1,
       const float* __restrict__ Wf, const float* __restrict__ bf) {
    int t = threadIdx.x;                // 0..511
    int o = t >> 5, c = t & 31;
    float acc = 0.f;
#pragma unroll
    for (int k = 0; k < CF; ++k) acc += W1[o*CF + k] * Wf[k*CC + c];
    g_W1f[o*CF + c] = acc;
    if (t < CHN) {
        float a = b1[t];
#pragma unroll
        for (int k = 0; k < CF; ++k) a += W1[t*CF + k] * bf[k];
        g_b1f[t] = a;
    }
    if (t < 64) {
        g_Sa[t] = 0.f; g_Sb[t] = 0.f;
        g_Qa[t] = 0.f; g_Qab[t] = 0.f; g_Qb[t] = 0.f;
    }
    __syncthreads();
    if (t == 0) {
        // Scan with the EXACT float formula used everywhere (bucket-consistent).
        int cur = 0;
        for (int tt = 0; tt < FT; ++tt) {
            float pos = (float)tt * T_SCALE;
            int i0 = (int)floorf(pos);
            if (i0 > 63) i0 = 63;
            float w = pos - (float)i0;
            while (cur <= i0) g_tstart[cur++] = tt;
            float u = 1.f - w;
            g_Sa[i0]  += u;      g_Sb[i0]  += w;
            g_Qa[i0]  += u*u;    g_Qab[i0] += u*w;   g_Qb[i0] += w*w;
        }
        while (cur <= 64) g_tstart[cur++] = FT;
    }
}

// ---------------------------------------------------------------------------
// K1: r[b][t][hw] = sum_c Wr[c]*x[b][c][t][hw] + br   (one full read of x, 67MB)
__global__ void __launch_bounds__(256)
k_r(const float* __restrict__ x, const float* __restrict__ Wr,
    const float* __restrict__ br) {
    int gid = blockIdx.x * blockDim.x + threadIdx.x;     // < B*T*HW = 524288
    int hw = gid & (HWSZ-1);
    int bt = gid >> 12;                                  // b*T + t
    int b  = bt >> 6, t = bt & 63;
    const float* xp = x + ((size_t)b*CC*TT + t)*HWSZ + hw;
    float acc = __ldg(br);
#pragma unroll
    for (int c = 0; c < CC; ++c)
        acc += __ldg(Wr + c) * xp[(size_t)c*TT*HWSZ];
    g_r[gid] = acc;
}

// ---------------------------------------------------------------------------
// K2: fused gather + projection at SOURCE resolution:
//     hx[b][o][t][n] = sum_c W1f[o][c] * x[b][c][t][coord_n] + b1f[o]
// grid = B*T = 128, block = 512 (n)
__global__ void __launch_bounds__(512)
k_hxg(const float* __restrict__ x, const int* __restrict__ coord) {
    __shared__ float sW[CHN*CF];
    __shared__ float sb[CHN];
    int tid = threadIdx.x;
    if (tid < CHN*CF) sW[tid] = g_W1f[tid];
    if (tid < CHN)    sb[tid] = g_b1f[tid];
    int bt = blockIdx.x;
    int b = bt >> 6, t = bt & 63;
    __syncthreads();

    int n = tid;
    int ch = __ldg(coord + ((size_t)(b*NN + n))*2);
    int cw = __ldg(coord + ((size_t)(b*NN + n))*2 + 1);
    const float* xp = x + ((size_t)(b*CC)*TT + t)*HWSZ + ch*WW + cw;

    float hv[CHN];
#pragma unroll
    for (int o = 0; o < CHN; ++o) hv[o] = sb[o];
#pragma unroll
    for (int c = 0; c < CC; ++c) {
        float v = __ldg(xp + (size_t)c*TT*HWSZ);
#pragma unroll
        for (int o = 0; o < CHN; ++o) hv[o] += sW[o*CF + c] * v;
    }
    float* hp = g_hx + (((size_t)b*CHN)*TT + t)*NN + n;
#pragma unroll
    for (int o = 0; o < CHN; ++o) hp[(size_t)o*TT*NN] = hv[o];
}

// ---------------------------------------------------------------------------
// K3: analytic BN stats over the (virtual) interpolated h, directly from hx.
// grid = B*64 (interval buckets), block = 512 (n)
__global__ void __launch_bounds__(512)
k_stats() {
    __shared__ float redS[CHN][16];
    __shared__ float redQ[CHN][16];
    int tid = threadIdx.x;
    int blk = blockIdx.x;
    int b = blk >> 6, s = blk & 63;
    int s1 = min(s + 1, TT - 1);
    float Sa = g_Sa[s], Sb = g_Sb[s];
    float Qa = g_Qa[s], Qab = g_Qab[s], Qb = g_Qb[s];

    int n = tid;
    const float* pa = g_hx + ((size_t)b*CHN)*TT*NN + (size_t)s *NN + n;
    const float* pb = g_hx + ((size_t)b*CHN)*TT*NN + (size_t)s1*NN + n;
    int warp = tid >> 5, lane = tid & 31;
#pragma unroll
    for (int o = 0; o < CHN; ++o) {
        float a = pa[(size_t)o*TT*NN];
        float c = pb[(size_t)o*TT*NN];
        float v = Sa*a + Sb*c;
        float q = Qa*a*a + 2.f*Qab*a*c + Qb*c*c;
#pragma unroll
        for (int off = 16; off; off >>= 1) {
            v += __shfl_down_sync(0xffffffffu, v, off);
            q += __shfl_down_sync(0xffffffffu, q, off);
        }
        if (lane == 0) { redS[o][warp] = v; redQ[o][warp] = q; }
    }
    __syncthreads();
    if (tid < 32) {
        int o = tid & 15;
        bool sq = tid >= 16;
        float a = 0.f;
#pragma unroll
        for (int wp = 0; wp < 16; ++wp)
            a += sq ? redQ[o][wp] : redS[o][wp];
        g_part[blk*32 + tid] = a;
    }
}

// ---------------------------------------------------------------------------
// K3b: deterministic reduction of 128 partials -> g_stats[32]
__global__ void __launch_bounds__(128)
k_redstats() {
    __shared__ float sm[128];
    int s = blockIdx.x;                 // 0..31
    float a = 0.f;
    for (int i = threadIdx.x; i < NBLK_S; i += 128)
        a += g_part[i*32 + s];
    sm[threadIdx.x] = a;
    __syncthreads();
    for (int off = 64; off; off >>= 1) {
        if (threadIdx.x < off) sm[threadIdx.x] += sm[threadIdx.x + off];
        __syncthreads();
    }
    if (threadIdx.x == 0) g_stats[s] = sm[0];
}

// ---------------------------------------------------------------------------
// K4: out = W2 @ relu(BN(lerp_t(hx))) + b2, grouped by source interval so each
// thread loads its two hx rows ONCE into registers and emits all mapped t's.
// grid = B*64, block = 256; each thread handles 2 n positions (n, n+256).
__global__ void __launch_bounds__(256)
k_out(const float* __restrict__ gamma, const float* __restrict__ beta,
      const float* __restrict__ W2, const float* __restrict__ b2,
      float* __restrict__ out) {
    __shared__ float sW2[CHN*CHN];
    __shared__ float sb2[CHN];
    __shared__ float sScale[CHN];
    __shared__ float sShift[CHN];
    int tid = threadIdx.x;
    if (tid < CHN*CHN) sW2[tid] = W2[tid];
    if (tid < CHN) {
        sb2[tid] = b2[tid];
        float mu  = g_stats[tid] / (float)BL;
        float var = g_stats[16 + tid] / (float)BL - mu*mu;
        float inv = rsqrtf(var + EPS);
        float sc  = gamma[tid] * inv;
        sScale[tid] = sc;
        sShift[tid] = beta[tid] - mu*sc;
    }
    __syncthreads();

    int blk = blockIdx.x;
    int b = blk >> 6, s = blk & 63;
    int t0 = g_tstart[s], t1 = g_tstart[s+1];
    if (t0 >= t1) return;
    int s1 = min(s + 1, TT - 1);

#pragma unroll
    for (int half = 0; half < 2; ++half) {
        int n = tid + half * 256;
        const float* pa = g_hx + ((size_t)b*CHN)*TT*NN + (size_t)s *NN + n;
        const float* pb = g_hx + ((size_t)b*CHN)*TT*NN + (size_t)s1*NN + n;
        float av[CHN], dv[CHN];
#pragma unroll
        for (int o = 0; o < CHN; ++o) {
            av[o] = pa[(size_t)o*TT*NN];
            dv[o] = pb[(size_t)o*TT*NN] - av[o];   // delta form: one FMA in loop
        }

        for (int t = t0; t < t1; ++t) {
            float pos = (float)t * T_SCALE;
            float w = pos - floorf(pos);
            float v[CHN];
#pragma unroll
            for (int o = 0; o < CHN; ++o) {
                float h = av[o] + dv[o] * w;
                v[o] = fmaxf(h * sScale[o] + sShift[o], 0.f);
            }
            float* op = out + (size_t)b*CHN*LL + (size_t)t*NN + n;
#pragma unroll
            for (int o2 = 0; o2 < CHN; ++o2) {
                float a = sb2[o2];
#pragma unroll
                for (int o = 0; o < CHN; ++o) a += sW2[o2*CHN + o] * v[o];
                op[(size_t)o2*LL] = a;
            }
        }
    }
}

// ---------------------------------------------------------------------------
// K5: result[b][0][t][hw] = lerp_t(r)     (t: 64 -> 400)
__global__ void __launch_bounds__(256)
k_result(float* __restrict__ outR) {
    int gid = blockIdx.x * blockDim.x + threadIdx.x;     // < B*FT*HW = 3276800
    int hw = gid & (HWSZ-1);
    int bt = gid >> 12;                                  // b*FT + t
    int b = bt / FT, t = bt - b*FT;
    float pos = (float)t * T_SCALE;
    int i0 = (int)floorf(pos);
    float w = pos - (float)i0;
    int i1 = min(i0 + 1, TT - 1);
    float a = g_r[((size_t)b*TT + i0)*HWSZ + hw];
    float c = g_r[((size_t)b*TT + i1)*HWSZ + hw];
    outR[gid] = a + (c - a) * w;
}

// ---------------------------------------------------------------------------
extern "C" void kernel_launch(void* const* d_in, const int* in_sizes, int n_in,
                              void* d_out, int out_size) {
    const float* x     = (const float*)d_in[0];
    const int*   coord = (const int*)  d_in[1];
    const float* Wf    = (const float*)d_in[2];
    const float* bf    = (const float*)d_in[3];
    const float* Wr    = (const float*)d_in[4];
    const float* br    = (const float*)d_in[5];
    const float* W1    = (const float*)d_in[6];
    const float* b1    = (const float*)d_in[7];
    const float* gamma = (const float*)d_in[8];
    const float* beta  = (const float*)d_in[9];
    const float* W2    = (const float*)d_in[10];
    const float* b2    = (const float*)d_in[11];

    float* out  = (float*)d_out;                 // [B,CH,L]   = 6,553,600 floats
    float* outR = out + (size_t)BB*CHN*LL;       // [B,1,FT,H,W] = 3,276,800 floats

    k_prep<<<1, 512>>>(W1, b1, Wf, bf);
    k_r<<<(BB*TT*HWSZ)/256, 256>>>(x, Wr, br);          // streams x; warms L2
    k_hxg<<<BB*TT, 512>>>(x, coord);                    // gather hits L2
    k_stats<<<BB*TT, 512>>>();
    k_redstats<<<32, 128>>>();
    k_out<<<BB*TT, 256>>>(gamma, beta, W2, b2, out);
    k_result<<<(BB*FT*HWSZ)/256, 256>>>(outR);
}

// round 8
// speedup vs baseline: 2.8540x; 2.8540x over previous
#include <cuda_runtime.h>

// Problem constants (fixed by setup_inputs)
#define BB  2
#define CC  32
#define TT  64
#define HH  64
#define WW  64
#define HWSZ 4096          // H*W
#define NN  512
#define CF  32
#define CHN 16
#define FT  400            // featT == orgt == 400
#define LL  (FT*NN)        // 204800
#define BL  (BB*LL)        // 409600
#define NBLK_S 256         // stat blocks
#define T_SCALE (63.0f/399.0f)
#define EPS 1e-5f

// Scratch (static device allocations; no cudaMalloc allowed)
__device__ float g_hx[BB*CHN*TT*NN];    // W1f@gather(x) at source T: [b][o][t][n]  4 MB
__device__ float g_r [BB*TT*HWSZ];      // Wr@x head: [b][t][hw]   2 MB
__device__ float g_W1f[CHN*CF];
__device__ float g_b1f[CHN];
__device__ float g_part[NBLK_S*32];     // per-block partials (16 sum + 16 sumsq)
__device__ float g_stats[32];
// interpolation weight tables per source interval s (bucket = i0(t))
__device__ float g_Sa[64], g_Sb[64];               // sum weights
__device__ float g_Qa[64], g_Qab[64], g_Qb[64];    // sumsq weights
__device__ int   g_tstart[65];                     // t-range per bucket

// ---------------------------------------------------------------------------
// K0: fuse W1@Wf -> W1f, W1@bf + b1 -> b1f; PARALLEL per-bucket weight scan.
__global__ void __launch_bounds__(512)
k_prep(const float* __restrict__ W1, const float* __restrict__ b1,
       const float* __restrict__ Wf, const float* __restrict__ bf) {
    int t = threadIdx.x;                // 0..511
    int o = t >> 5, c = t & 31;
    float acc = 0.f;
#pragma unroll
    for (int k = 0; k < CF; ++k) acc += W1[o*CF + k] * Wf[k*CC + c];
    g_W1f[o*CF + c] = acc;
    if (t < CHN) {
        float a = b1[t];
#pragma unroll
        for (int k = 0; k < CF; ++k) a += W1[t*CF + k] * bf[k];
        g_b1f[t] = a;
    }
    if (t < 64) {
        int s = t;
        float Sa = 0.f, Sb = 0.f, Qa = 0.f, Qab = 0.f, Qb = 0.f;
        int tstart = FT;
        // EXACT float formula used everywhere (bucket-consistent), all in regs.
        for (int tt = 0; tt < FT; ++tt) {
            float pos = (float)tt * T_SCALE;
            int i0 = (int)floorf(pos);
            if (i0 > 63) i0 = 63;
            float w = pos - (float)i0;
            if (i0 >= s && tstart == FT) tstart = tt;
            if (i0 == s) {
                float u = 1.f - w;
                Sa += u;  Sb += w;
                Qa += u*u; Qab += u*w; Qb += w*w;
            }
        }
        g_Sa[s] = Sa; g_Sb[s] = Sb;
        g_Qa[s] = Qa; g_Qab[s] = Qab; g_Qb[s] = Qb;
        g_tstart[s] = tstart;
        if (s == 63) g_tstart[64] = FT;
    }
}

// ---------------------------------------------------------------------------
// K1: r[b][t][hw] = sum_c Wr[c]*x[b][c][t][hw] + br   (one full read of x, 67MB)
// float4 vectorized: thread per 4 hw.
__global__ void __launch_bounds__(256)
k_r(const float* __restrict__ x, const float* __restrict__ Wr,
    const float* __restrict__ br) {
    int gid = blockIdx.x * blockDim.x + threadIdx.x;     // < B*T*HW/4 = 131072
    int hw4 = gid & (HWSZ/4 - 1);                        // quad index within slice
    int bt  = gid >> 10;                                 // b*T + t
    int b   = bt >> 6, t = bt & 63;
    const float4* xp = (const float4*)(x + ((size_t)b*CC*TT + t)*HWSZ) + hw4;
    float brv = __ldg(br);
    float4 acc = make_float4(brv, brv, brv, brv);
#pragma unroll
    for (int c = 0; c < CC; ++c) {
        float wv = __ldg(Wr + c);
        float4 v = __ldg(xp + (size_t)c*TT*HWSZ/4);
        acc.x += wv*v.x; acc.y += wv*v.y; acc.z += wv*v.z; acc.w += wv*v.w;
    }
    ((float4*)g_r)[gid] = acc;
}

// ---------------------------------------------------------------------------
// K2: fused gather + projection at SOURCE resolution:
//     hx[b][o][t][n] = sum_c W1f[o][c] * x[b][c][t][coord_n] + b1f[o]
// grid = B*T*4 = 512 blocks, block = 128 (n-chunk)
__global__ void __launch_bounds__(128)
k_hxg(const float* __restrict__ x, const int* __restrict__ coord) {
    __shared__ float sW[CHN*CF];
    __shared__ float sb[CHN];
    int tid = threadIdx.x;
    for (int i = tid; i < CHN*CF; i += 128) sW[i] = g_W1f[i];
    if (tid < CHN) sb[tid] = g_b1f[tid];
    int blk = blockIdx.x;
    int nc = blk & 3;
    int bt = blk >> 2;
    int b = bt >> 6, t = bt & 63;
    __syncthreads();

    int n = nc*128 + tid;
    int ch = __ldg(coord + ((size_t)(b*NN + n))*2);
    int cw = __ldg(coord + ((size_t)(b*NN + n))*2 + 1);
    const float* xp = x + ((size_t)(b*CC)*TT + t)*HWSZ + ch*WW + cw;

    float hv[CHN];
#pragma unroll
    for (int o = 0; o < CHN; ++o) hv[o] = sb[o];
#pragma unroll
    for (int c = 0; c < CC; ++c) {
        float v = __ldg(xp + (size_t)c*TT*HWSZ);
#pragma unroll
        for (int o = 0; o < CHN; ++o) hv[o] += sW[o*CF + c] * v;
    }
    float* hp = g_hx + (((size_t)b*CHN)*TT + t)*NN + n;
#pragma unroll
    for (int o = 0; o < CHN; ++o) hp[(size_t)o*TT*NN] = hv[o];
}

// ---------------------------------------------------------------------------
// K3: analytic BN stats over the (virtual) interpolated h, directly from hx.
// grid = 256 blocks (b, s, n-half), block = 256
__global__ void __launch_bounds__(256)
k_stats() {
    __shared__ float redS[CHN][8];
    __shared__ float redQ[CHN][8];
    int tid = threadIdx.x;
    int blk = blockIdx.x;
    int b = blk >> 7;
    int r = blk & 127;
    int s = r >> 1;
    int nc = r & 1;
    int s1 = min(s + 1, TT - 1);
    float Sa = g_Sa[s], Sb = g_Sb[s];
    float Qa = g_Qa[s], Qab = g_Qab[s], Qb = g_Qb[s];

    int n = nc*256 + tid;
    const float* pa = g_hx + ((size_t)b*CHN)*TT*NN + (size_t)s *NN + n;
    const float* pb = g_hx + ((size_t)b*CHN)*TT*NN + (size_t)s1*NN + n;
    int warp = tid >> 5, lane = tid & 31;
#pragma unroll
    for (int o = 0; o < CHN; ++o) {
        float a = pa[(size_t)o*TT*NN];
        float c = pb[(size_t)o*TT*NN];
        float v = Sa*a + Sb*c;
        float q = Qa*a*a + 2.f*Qab*a*c + Qb*c*c;
#pragma unroll
        for (int off = 16; off; off >>= 1) {
            v += __shfl_down_sync(0xffffffffu, v, off);
            q += __shfl_down_sync(0xffffffffu, q, off);
        }
        if (lane == 0) { redS[o][warp] = v; redQ[o][warp] = q; }
    }
    __syncthreads();
    if (tid < 32) {
        int o = tid & 15;
        bool sq = tid >= 16;
        float a = 0.f;
#pragma unroll
        for (int wp = 0; wp < 8; ++wp)
            a += sq ? redQ[o][wp] : redS[o][wp];
        g_part[blk*32 + tid] = a;
    }
}

// ---------------------------------------------------------------------------
// K3b: deterministic reduction of 256 partials -> g_stats[32]
__global__ void __launch_bounds__(128)
k_redstats() {
    __shared__ float sm[128];
    int s = blockIdx.x;                 // 0..31
    float a = 0.f;
    for (int i = threadIdx.x; i < NBLK_S; i += 128)
        a += g_part[i*32 + s];
    sm[threadIdx.x] = a;
    __syncthreads();
    for (int off = 64; off; off >>= 1) {
        if (threadIdx.x < off) sm[threadIdx.x] += sm[threadIdx.x + off];
        __syncthreads();
    }
    if (threadIdx.x == 0) g_stats[s] = sm[0];
}

// ---------------------------------------------------------------------------
// K4: out = W2 @ relu(BN(lerp_t(hx))) + b2, grouped by source interval so each
// thread loads its two hx rows ONCE into registers and emits all mapped t's.
// grid = B*64*4 = 512 blocks, block = 128 (n-chunk)
__global__ void __launch_bounds__(128)
k_out(const float* __restrict__ gamma, const float* __restrict__ beta,
      const float* __restrict__ W2, const float* __restrict__ b2,
      float* __restrict__ out) {
    __shared__ float sW2[CHN*CHN];
    __shared__ float sb2[CHN];
    __shared__ float sScale[CHN];
    __shared__ float sShift[CHN];
    int tid = threadIdx.x;
    for (int i = tid; i < CHN*CHN; i += 128) sW2[i] = W2[i];
    if (tid < CHN) {
        sb2[tid] = b2[tid];
        float mu  = g_stats[tid] / (float)BL;
        float var = g_stats[16 + tid] / (float)BL - mu*mu;
        float inv = rsqrtf(var + EPS);
        float sc  = gamma[tid] * inv;
        sScale[tid] = sc;
        sShift[tid] = beta[tid] - mu*sc;
    }
    __syncthreads();

    int blk = blockIdx.x;
    int nc = blk & 3;
    int bs = blk >> 2;
    int b = bs >> 6, s = bs & 63;
    int t0 = g_tstart[s], t1 = g_tstart[s+1];
    if (t0 >= t1) return;
    int s1 = min(s + 1, TT - 1);

    int n = nc*128 + tid;
    const float* pa = g_hx + ((size_t)b*CHN)*TT*NN + (size_t)s *NN + n;
    const float* pb = g_hx + ((size_t)b*CHN)*TT*NN + (size_t)s1*NN + n;
    float av[CHN], dv[CHN];
#pragma unroll
    for (int o = 0; o < CHN; ++o) {
        av[o] = pa[(size_t)o*TT*NN];
        dv[o] = pb[(size_t)o*TT*NN] - av[o];   // delta form: one FMA in loop
    }

    for (int t = t0; t < t1; ++t) {
        float pos = (float)t * T_SCALE;
        float w = pos - floorf(pos);
        float v[CHN];
#pragma unroll
        for (int o = 0; o < CHN; ++o) {
            float h = av[o] + dv[o] * w;
            v[o] = fmaxf(h * sScale[o] + sShift[o], 0.f);
        }
        float* op = out + (size_t)b*CHN*LL + (size_t)t*NN + n;
#pragma unroll
        for (int o2 = 0; o2 < CHN; ++o2) {
            float a = sb2[o2];
#pragma unroll
            for (int o = 0; o < CHN; ++o) a += sW2[o2*CHN + o] * v[o];
            op[(size_t)o2*LL] = a;
        }
    }
}

// ---------------------------------------------------------------------------
// K5: result[b][0][t][hw] = lerp_t(r)  (t: 64->400), float4 vectorized
__global__ void __launch_bounds__(256)
k_result(float* __restrict__ outR) {
    int gid = blockIdx.x * blockDim.x + threadIdx.x;     // < B*FT*HW/4 = 819200
    int hw4 = gid & (HWSZ/4 - 1);
    int bt  = gid >> 10;                                 // b*FT + t
    int b = bt / FT, t = bt - b*FT;
    float pos = (float)t * T_SCALE;
    int i0 = (int)floorf(pos);
    float w = pos - (float)i0;
    int i1 = min(i0 + 1, TT - 1);
    float4 a = ((const float4*)g_r)[((size_t)b*TT + i0)*(HWSZ/4) + hw4];
    float4 c = ((const float4*)g_r)[((size_t)b*TT + i1)*(HWSZ/4) + hw4];
    float4 o;
    o.x = a.x + (c.x - a.x)*w;
    o.y = a.y + (c.y - a.y)*w;
    o.z = a.z + (c.z - a.z)*w;
    o.w = a.w + (c.w - a.w)*w;
    ((float4*)outR)[gid] = o;
}

// ---------------------------------------------------------------------------
extern "C" void kernel_launch(void* const* d_in, const int* in_sizes, int n_in,
                              void* d_out, int out_size) {
    const float* x     = (const float*)d_in[0];
    const int*   coord = (const int*)  d_in[1];
    const float* Wf    = (const float*)d_in[2];
    const float* bf    = (const float*)d_in[3];
    const float* Wr    = (const float*)d_in[4];
    const float* br    = (const float*)d_in[5];
    const float* W1    = (const float*)d_in[6];
    const float* b1    = (const float*)d_in[7];
    const float* gamma = (const float*)d_in[8];
    const float* beta  = (const float*)d_in[9];
    const float* W2    = (const float*)d_in[10];
    const float* b2    = (const float*)d_in[11];

    float* out  = (float*)d_out;                 // [B,CH,L]   = 6,553,600 floats
    float* outR = out + (size_t)BB*CHN*LL;       // [B,1,FT,H,W] = 3,276,800 floats

    k_prep<<<1, 512>>>(W1, b1, Wf, bf);
    k_r<<<(BB*TT*HWSZ/4)/256, 256>>>(x, Wr, br);        // streams x; warms L2
    k_hxg<<<BB*TT*4, 128>>>(x, coord);                  // gather hits L2
    k_stats<<<NBLK_S, 256>>>();
    k_redstats<<<32, 128>>>();
    k_out<<<BB*TT*4, 128>>>(gamma, beta, W2, b2, out);
    k_result<<<(BB*FT*HWSZ/4)/256, 256>>>(outR);
}

// round 9
// speedup vs baseline: 3.0078x; 1.0539x over previous
#include <cuda_runtime.h>

// Problem constants (fixed by setup_inputs)
#define BB  2
#define CC  32
#define TT  64
#define HH  64
#define WW  64
#define HWSZ 4096          // H*W
#define NN  512
#define CF  32
#define CHN 16
#define FT  400            // featT == orgt == 400
#define LL  (FT*NN)        // 204800
#define BL  (BB*LL)        // 409600
#define T_SCALE (63.0f/399.0f)
#define EPS 1e-5f

#define NBLK_HXG 256       // (b,t,nc) blocks in k_main
#define NBLK_R   512       // float4 r blocks in k_main
#define NBLK_ST  64        // (b,o,nc) blocks in k_stats2
#define NBLK_OUT 256       // (b,s,nc) blocks in k_final
#define NBLK_RES 3200      // float4 result blocks in k_final

// Scratch (static device allocations; no cudaMalloc allowed)
__device__ float g_hx[BB*CHN*TT*NN];    // W1f@gather(x) at source T: [b][o][t][n]  4 MB
__device__ float g_r [BB*TT*HWSZ];      // Wr@x head: [b][t][hw]   2 MB
__device__ float g_W1f[CHN*CF];
__device__ float g_b1f[CHN];
__device__ float g_part[NBLK_ST*2];     // per-block (sum, sumsq)
// per-source-row stat coefficient tables + t-range per bucket
__device__ float g_rowA[64], g_rowQ[64], g_cross[64];
__device__ int   g_tstart[65];

// ---------------------------------------------------------------------------
// K0: fuse W1@Wf -> W1f, W1@bf + b1 -> b1f; parallel per-bucket weight scan,
// then fold bucket weights into per-source-row coefficients.
__global__ void __launch_bounds__(512)
k_prep(const float* __restrict__ W1, const float* __restrict__ b1,
       const float* __restrict__ Wf, const float* __restrict__ bf) {
    __shared__ float sSa[64], sSb[64], sQa[64], sQab[64], sQb[64];
    int t = threadIdx.x;                // 0..511
    int o = t >> 5, c = t & 31;
    float acc = 0.f;
#pragma unroll
    for (int k = 0; k < CF; ++k) acc += W1[o*CF + k] * Wf[k*CC + c];
    g_W1f[o*CF + c] = acc;
    if (t < CHN) {
        float a = b1[t];
#pragma unroll
        for (int k = 0; k < CF; ++k) a += W1[t*CF + k] * bf[k];
        g_b1f[t] = a;
    }
    if (t < 64) {
        int s = t;
        float Sa = 0.f, Sb = 0.f, Qa = 0.f, Qab = 0.f, Qb = 0.f;
        int tstart = FT;
        // EXACT float formula used everywhere (bucket-consistent), all in regs.
        for (int tt = 0; tt < FT; ++tt) {
            float pos = (float)tt * T_SCALE;
            int i0 = (int)floorf(pos);
            if (i0 > 63) i0 = 63;
            float w = pos - (float)i0;
            if (i0 >= s && tstart == FT) tstart = tt;
            if (i0 == s) {
                float u = 1.f - w;
                Sa += u;  Sb += w;
                Qa += u*u; Qab += u*w; Qb += w*w;
            }
        }
        sSa[s] = Sa; sSb[s] = Sb; sQa[s] = Qa; sQab[s] = Qab; sQb[s] = Qb;
        g_tstart[s] = tstart;
        if (s == 63) g_tstart[64] = FT;
    }
    __syncthreads();
    if (t < 64) {
        // Fold bucket weights into per-source-row coefficients.
        // Row t receives: Sa[t] (as interval-t left end), Sb[t-1] (right end of t-1),
        // and for t==63 additionally Sb[63] since s1=min(64,63)=63 (self-pair).
        float rA = sSa[t] + (t > 0 ? sSb[t-1] : 0.f) + (t == 63 ? sSb[63] : 0.f);
        float rQ = sQa[t] + (t > 0 ? sQb[t-1] : 0.f)
                 + (t == 63 ? (sQb[63] + 2.f*sQab[63]) : 0.f);
        g_rowA[t]  = rA;
        g_rowQ[t]  = rQ;
        g_cross[t] = (t < 63) ? 2.f*sQab[t] : 0.f;   // couples rows t and t+1
    }
}

// ---------------------------------------------------------------------------
// K_MAIN: fused independent kernels.
//   blocks [0, 256):      hxg — hx[b][o][t][n] = W1f @ x[b][:,t,coord_n] + b1f
//   blocks [256, 768):    r   — r[b][t][hw] = Wr @ x (float4)
__global__ void __launch_bounds__(256)
k_main(const float* __restrict__ x, const int* __restrict__ coord,
       const float* __restrict__ Wr, const float* __restrict__ br) {
    int tid = threadIdx.x;
    if (blockIdx.x < NBLK_HXG) {
        __shared__ float sW[CHN*CF];
        __shared__ float sb[CHN];
        for (int i = tid; i < CHN*CF; i += 256) sW[i] = g_W1f[i];
        if (tid < CHN) sb[tid] = g_b1f[tid];
        int blk = blockIdx.x;
        int nc = blk & 1;
        int bt = blk >> 1;
        int b = bt >> 6, t = bt & 63;
        __syncthreads();

        int n = nc*256 + tid;
        int ch = __ldg(coord + ((size_t)(b*NN + n))*2);
        int cw = __ldg(coord + ((size_t)(b*NN + n))*2 + 1);
        const float* xp = x + ((size_t)(b*CC)*TT + t)*HWSZ + ch*WW + cw;

        float hv[CHN];
#pragma unroll
        for (int o = 0; o < CHN; ++o) hv[o] = sb[o];
#pragma unroll
        for (int c = 0; c < CC; ++c) {
            float v = __ldg(xp + (size_t)c*TT*HWSZ);
#pragma unroll
            for (int o = 0; o < CHN; ++o) hv[o] += sW[o*CF + c] * v;
        }
        float* hp = g_hx + (((size_t)b*CHN)*TT + t)*NN + n;
#pragma unroll
        for (int o = 0; o < CHN; ++o) hp[(size_t)o*TT*NN] = hv[o];
    } else {
        int gid = (blockIdx.x - NBLK_HXG) * 256 + tid;   // < B*T*HW/4 = 131072
        int hw4 = gid & (HWSZ/4 - 1);
        int bt  = gid >> 10;                             // b*T + t
        int b   = bt >> 6, t = bt & 63;
        const float4* xp = (const float4*)(x + ((size_t)b*CC*TT + t)*HWSZ) + hw4;
        float brv = __ldg(br);
        float4 acc = make_float4(brv, brv, brv, brv);
#pragma unroll
        for (int c = 0; c < CC; ++c) {
            float wv = __ldg(Wr + c);
            float4 v = __ldg(xp + (size_t)c*TT*HWSZ/4);
            acc.x += wv*v.x; acc.y += wv*v.y; acc.z += wv*v.z; acc.w += wv*v.w;
        }
        ((float4*)g_r)[gid] = acc;
    }
}

// ---------------------------------------------------------------------------
// K_STATS2: per-(b,o,nc) block; each thread walks t serially over its n,
// accumulating row-weighted sum and sumsq (incl. cross term) in registers.
// grid = 64, block = 256
__global__ void __launch_bounds__(256)
k_stats2() {
    __shared__ float sA[64], sQ[64], sX[64];
    __shared__ float red[8][2];
    int tid = threadIdx.x;
    if (tid < 64)               sA[tid]      = g_rowA[tid];
    else if (tid < 128)         sQ[tid-64]   = g_rowQ[tid-64];
    else if (tid < 192)         sX[tid-128]  = g_cross[tid-128];
    int blk = blockIdx.x;
    int b  = blk >> 5;
    int o  = (blk >> 1) & 15;
    int nc = blk & 1;
    int n  = nc*256 + tid;
    __syncthreads();

    const float* hp = g_hx + (((size_t)b*CHN + o)*TT)*NN + n;
    float v = 0.f, q = 0.f;
    float cur = hp[0];
#pragma unroll 8
    for (int t = 0; t < 63; ++t) {
        float nxt = hp[(size_t)(t+1)*NN];
        v += sA[t]*cur;
        q += sQ[t]*cur*cur + sX[t]*cur*nxt;
        cur = nxt;
    }
    v += sA[63]*cur;
    q += sQ[63]*cur*cur;

    int warp = tid >> 5, lane = tid & 31;
#pragma unroll
    for (int off = 16; off; off >>= 1) {
        v += __shfl_down_sync(0xffffffffu, v, off);
        q += __shfl_down_sync(0xffffffffu, q, off);
    }
    if (lane == 0) { red[warp][0] = v; red[warp][1] = q; }
    __syncthreads();
    if (tid < 2) {
        float a = 0.f;
#pragma unroll
        for (int wp = 0; wp < 8; ++wp) a += red[wp][tid];
        g_part[blk*2 + tid] = a;
    }
}

// ---------------------------------------------------------------------------
// K_FINAL: fused output kernels.
//   blocks [0, 256):        out — W2 @ relu(BN(lerp_t(hx))) + b2, per (b,s,nc)
//   blocks [256, 3456):     result — lerp_t(r) (float4)
__global__ void __launch_bounds__(256)
k_final(const float* __restrict__ gamma, const float* __restrict__ beta,
        const float* __restrict__ W2, const float* __restrict__ b2,
        float* __restrict__ out, float* __restrict__ outR) {
    int tid = threadIdx.x;
    if (blockIdx.x < NBLK_OUT) {
        __shared__ float sW2[CHN*CHN];
        __shared__ float sb2[CHN];
        __shared__ float sScale[CHN];
        __shared__ float sShift[CHN];
        for (int i = tid; i < CHN*CHN; i += 256) sW2[i] = W2[i];
        if (tid < CHN) {
            int o = tid;
            sb2[o] = b2[o];
            // Deterministic fixed-order reduction of the 4 (b,nc) partials.
            float sv = 0.f, sq = 0.f;
#pragma unroll
            for (int b = 0; b < BB; ++b)
#pragma unroll
                for (int nc = 0; nc < 2; ++nc) {
                    int pb = b*32 + o*2 + nc;
                    sv += g_part[pb*2];
                    sq += g_part[pb*2 + 1];
                }
            float mu  = sv / (float)BL;
            float var = sq / (float)BL - mu*mu;
            float inv = rsqrtf(var + EPS);
            float sc  = gamma[o] * inv;
            sScale[o] = sc;
            sShift[o] = beta[o] - mu*sc;
        }
        __syncthreads();

        int blk = blockIdx.x;
        int nc = blk & 1;
        int bs = blk >> 1;
        int b = bs >> 6, s = bs & 63;
        int t0 = g_tstart[s], t1 = g_tstart[s+1];
        if (t0 >= t1) return;
        int s1 = min(s + 1, TT - 1);

        int n = nc*256 + tid;
        const float* pa = g_hx + ((size_t)b*CHN)*TT*NN + (size_t)s *NN + n;
        const float* pb = g_hx + ((size_t)b*CHN)*TT*NN + (size_t)s1*NN + n;
        float av[CHN], dv[CHN];
#pragma unroll
        for (int o = 0; o < CHN; ++o) {
            av[o] = pa[(size_t)o*TT*NN];
            dv[o] = pb[(size_t)o*TT*NN] - av[o];
        }

        for (int t = t0; t < t1; ++t) {
            float pos = (float)t * T_SCALE;
            float w = pos - floorf(pos);
            float v[CHN];
#pragma unroll
            for (int o = 0; o < CHN; ++o) {
                float h = av[o] + dv[o] * w;
                v[o] = fmaxf(h * sScale[o] + sShift[o], 0.f);
            }
            float* op = out + (size_t)b*CHN*LL + (size_t)t*NN + n;
#pragma unroll
            for (int o2 = 0; o2 < CHN; ++o2) {
                float a = sb2[o2];
#pragma unroll
                for (int o = 0; o < CHN; ++o) a += sW2[o2*CHN + o] * v[o];
                op[(size_t)o2*LL] = a;
            }
        }
    } else {
        int gid = (blockIdx.x - NBLK_OUT) * 256 + tid;   // < B*FT*HW/4 = 819200
        int hw4 = gid & (HWSZ/4 - 1);
        int bt  = gid >> 10;                             // b*FT + t
        int b = bt / FT, t = bt - b*FT;
        float pos = (float)t * T_SCALE;
        int i0 = (int)floorf(pos);
        float w = pos - (float)i0;
        int i1 = min(i0 + 1, TT - 1);
        float4 a = ((const float4*)g_r)[((size_t)b*TT + i0)*(HWSZ/4) + hw4];
        float4 c = ((const float4*)g_r)[((size_t)b*TT + i1)*(HWSZ/4) + hw4];
        float4 o;
        o.x = a.x + (c.x - a.x)*w;
        o.y = a.y + (c.y - a.y)*w;
        o.z = a.z + (c.z - a.z)*w;
        o.w = a.w + (c.w - a.w)*w;
        ((float4*)outR)[gid] = o;
    }
}

// ---------------------------------------------------------------------------
extern "C" void kernel_launch(void* const* d_in, const int* in_sizes, int n_in,
                              void* d_out, int out_size) {
    const float* x     = (const float*)d_in[0];
    const int*   coord = (const int*)  d_in[1];
    const float* Wf    = (const float*)d_in[2];
    const float* bf    = (const float*)d_in[3];
    const float* Wr    = (const float*)d_in[4];
    const float* br    = (const float*)d_in[5];
    const float* W1    = (const float*)d_in[6];
    const float* b1    = (const float*)d_in[7];
    const float* gamma = (const float*)d_in[8];
    const float* beta  = (const float*)d_in[9];
    const float* W2    = (const float*)d_in[10];
    const float* b2    = (const float*)d_in[11];

    float* out  = (float*)d_out;                 // [B,CH,L]   = 6,553,600 floats
    float* outR = out + (size_t)BB*CHN*LL;       // [B,1,FT,H,W] = 3,276,800 floats

    k_prep<<<1, 512>>>(W1, b1, Wf, bf);
    k_main<<<NBLK_HXG + NBLK_R, 256>>>(x, coord, Wr, br);
    k_stats2<<<NBLK_ST, 256>>>();
    k_final<<<NBLK_OUT + NBLK_RES, 256>>>(gamma, beta, W2, b2, out, outR);
}